// round 4
// baseline (speedup 1.0000x reference)
#include <cuda_runtime.h>
#include <cuda_bf16.h>
#include <math.h>
#include <stdint.h>

#define NNODES 50000
#define NEDGES 800000
#define HID    128
#define NLAYERS 3
#define NGRAPHS 256
#define BN_EPS 1e-5f

// ---------------- scratch ----------------
__device__ float g_h[NNODES * HID];
__device__ float g_t[NNODES * HID];
__device__ float g_s[NNODES * HID];
__device__ float g_gi[NNODES * 3 * HID];
__device__ float g_gh[NNODES * 3 * HID];
__device__ float g_deg[NNODES];
__device__ int   g_offs[NGRAPHS + 1];
__device__ float g_z[NGRAPHS * 2 * HID];

// ---------------- packed f32x2 helpers ----------------
__device__ __forceinline__ double pack2(float lo, float hi) {
    double d;
    asm("mov.b64 %0, {%1, %2};" : "=d"(d) : "f"(lo), "f"(hi));
    return d;
}
__device__ __forceinline__ double fma2(double a, double b, double c) {
    double d;
    asm("fma.rn.f32x2 %0, %1, %2, %3;" : "=d"(d) : "d"(a), "d"(b), "d"(c));
    return d;
}
__device__ __forceinline__ void unpack2(double d, float& lo, float& hi) {
    asm("mov.b64 {%0, %1}, %2;" : "=f"(lo), "=f"(hi) : "d"(d));
}

// ---------------- K=128 fp32 GEMM via FFMA2 ----------------
// C[M,N] = A[M,128] @ B (+ bias[n]*(rowScale?rowScale[m]:1)) (optional relu)
// trans==0: B[k*ldb + n]  (weights [128,128])
// trans==1: B[n*ldb + k]  (weights [Ntot,128], e.g. GRU [384,128])
// Tiles BM=128, BN=128, K split in two 64-chunks. 256 threads.
// As stored transposed [k][m] so m-pairs are native f32x2 operands.
#define PITCH 132
#define GEMM_SMEM (2 * 64 * PITCH * 4)

__global__ void __launch_bounds__(256, 2)
gemm_k128_kernel(const float* __restrict__ A, const float* __restrict__ B,
                 float* __restrict__ C, int M, int N, int ldb, int trans,
                 const float* __restrict__ bias, const float* __restrict__ rowScale,
                 int doRelu)
{
    extern __shared__ float smem[];
    float* As = smem;                 // [64 k][132 m-pitch]
    float* Bs = smem + 64 * PITCH;    // [64 k][132 n-pitch]

    const int m0 = blockIdx.x * 128;
    const int n0 = blockIdx.y * 128;
    const int tid = threadIdx.x;
    const int tx = tid & 15;          // n-direction (8 n per thread)
    const int ty = tid >> 4;          // m-direction (8 m per thread)

    double acc[4][8];                 // [m-pair][n], each double = f32x2 (m, m+1)
#pragma unroll
    for (int i = 0; i < 4; ++i)
#pragma unroll
        for (int j = 0; j < 8; ++j) acc[i][j] = 0.0;

    for (int kc = 0; kc < 2; ++kc) {
        const int k0 = kc * 64;
        // --- A[m][k] -> As[k][m] (transposed) ---
        {
            const int k4 = tid & 15;       // float4 index along k
            const int mr = tid >> 4;
#pragma unroll
            for (int p = 0; p < 8; ++p) {
                const int m = mr + p * 16;
                const int gm = m0 + m;
                float4 v = make_float4(0.f, 0.f, 0.f, 0.f);
                if (gm < M)
                    v = *(const float4*)(A + (size_t)gm * 128 + k0 + k4 * 4);
                As[(k4 * 4 + 0) * PITCH + m] = v.x;
                As[(k4 * 4 + 1) * PITCH + m] = v.y;
                As[(k4 * 4 + 2) * PITCH + m] = v.z;
                As[(k4 * 4 + 3) * PITCH + m] = v.w;
            }
        }
        // --- B -> Bs[k][n] ---
        if (!trans) {
            const int n4 = tid & 31;
            const int kr = tid >> 5;
#pragma unroll
            for (int p = 0; p < 8; ++p) {
                const int k = kr + p * 8;
                float4 v = *(const float4*)(B + (size_t)(k0 + k) * ldb + n0 + n4 * 4);
                *(float4*)(&Bs[k * PITCH + n4 * 4]) = v;
            }
        } else {
            const int k4 = tid & 15;
            const int nr = tid >> 4;
#pragma unroll
            for (int p = 0; p < 8; ++p) {
                const int n = nr + p * 16;
                float4 v = *(const float4*)(B + (size_t)(n0 + n) * ldb + k0 + k4 * 4);
                Bs[(k4 * 4 + 0) * PITCH + n] = v.x;
                Bs[(k4 * 4 + 1) * PITCH + n] = v.y;
                Bs[(k4 * 4 + 2) * PITCH + n] = v.z;
                Bs[(k4 * 4 + 3) * PITCH + n] = v.w;
            }
        }
        __syncthreads();

#pragma unroll 4
        for (int k = 0; k < 64; ++k) {
            // A m-pairs: native f32x2 (16B-aligned: k*528B + ty*32B)
            const double2 a01 = *(const double2*)(&As[k * PITCH + ty * 8]);
            const double2 a23 = *(const double2*)(&As[k * PITCH + ty * 8 + 4]);
            const double ap[4] = {a01.x, a01.y, a23.x, a23.y};
            const float4 b0 = *(const float4*)(&Bs[k * PITCH + tx * 8]);
            const float4 b1 = *(const float4*)(&Bs[k * PITCH + tx * 8 + 4]);
            double bb[8];
            bb[0] = pack2(b0.x, b0.x); bb[1] = pack2(b0.y, b0.y);
            bb[2] = pack2(b0.z, b0.z); bb[3] = pack2(b0.w, b0.w);
            bb[4] = pack2(b1.x, b1.x); bb[5] = pack2(b1.y, b1.y);
            bb[6] = pack2(b1.z, b1.z); bb[7] = pack2(b1.w, b1.w);
#pragma unroll
            for (int i = 0; i < 4; ++i)
#pragma unroll
                for (int j = 0; j < 8; ++j)
                    acc[i][j] = fma2(ap[i], bb[j], acc[i][j]);
        }
        __syncthreads();
    }

    // --- epilogue ---
    float4 bia0 = make_float4(0.f, 0.f, 0.f, 0.f);
    float4 bia1 = make_float4(0.f, 0.f, 0.f, 0.f);
    if (bias) {
        bia0 = *(const float4*)(bias + n0 + tx * 8);
        bia1 = *(const float4*)(bias + n0 + tx * 8 + 4);
    }
    const float bf[8] = {bia0.x, bia0.y, bia0.z, bia0.w,
                         bia1.x, bia1.y, bia1.z, bia1.w};
#pragma unroll
    for (int i = 0; i < 4; ++i) {
        float lo[8], hi[8];
#pragma unroll
        for (int j = 0; j < 8; ++j) unpack2(acc[i][j], lo[j], hi[j]);
#pragma unroll
        for (int half = 0; half < 2; ++half) {
            const int m = m0 + ty * 8 + i * 2 + half;
            if (m >= M) continue;
            const float* src = half ? hi : lo;
            const float rs = rowScale ? rowScale[m] : 1.f;
            float o[8];
#pragma unroll
            for (int j = 0; j < 8; ++j) {
                o[j] = src[j] + bf[j] * rs;
                if (doRelu) o[j] = fmaxf(o[j], 0.f);
            }
            float* cp = C + (size_t)m * N + n0 + tx * 8;
            *(float4*)(cp)     = make_float4(o[0], o[1], o[2], o[3]);
            *(float4*)(cp + 4) = make_float4(o[4], o[5], o[6], o[7]);
        }
    }
}

// ---------------- per-edge: u = relu(t[src] + ea@W1e); s[dst] += u ----------
__global__ void __launch_bounds__(256)
edge_kernel(const int* __restrict__ ei, const float* __restrict__ ea,
            const float* __restrict__ t, float* __restrict__ s,
            const float* __restrict__ w1e)
{
    const int lane = threadIdx.x & 31;
    float4 w[16];
#pragma unroll
    for (int j = 0; j < 16; ++j)
        w[j] = *(const float4*)(w1e + j * 128 + lane * 4);

    const int warp = blockIdx.x * (blockDim.x >> 5) + (threadIdx.x >> 5);
    const int nw = gridDim.x * (blockDim.x >> 5);
    for (int e = warp; e < NEDGES; e += nw) {
        const int src = __ldg(ei + e);
        const int dst = __ldg(ei + NEDGES + e);
        float4 acc = *(const float4*)(t + (size_t)src * 128 + lane * 4);
        const float4* ev = (const float4*)(ea + (size_t)e * 16);
#pragma unroll
        for (int q = 0; q < 4; ++q) {
            const float4 e4 = __ldg(ev + q);
            const float4 w0 = w[q * 4 + 0], w1 = w[q * 4 + 1];
            const float4 w2 = w[q * 4 + 2], w3 = w[q * 4 + 3];
            acc.x += e4.x * w0.x + e4.y * w1.x + e4.z * w2.x + e4.w * w3.x;
            acc.y += e4.x * w0.y + e4.y * w1.y + e4.z * w2.y + e4.w * w3.y;
            acc.z += e4.x * w0.z + e4.y * w1.z + e4.z * w2.z + e4.w * w3.z;
            acc.w += e4.x * w0.w + e4.y * w1.w + e4.z * w2.w + e4.w * w3.w;
        }
        acc.x = fmaxf(acc.x, 0.f); acc.y = fmaxf(acc.y, 0.f);
        acc.z = fmaxf(acc.z, 0.f); acc.w = fmaxf(acc.w, 0.f);
        float* p = s + (size_t)dst * 128 + lane * 4;
        asm volatile("red.global.add.v4.f32 [%0], {%1,%2,%3,%4};"
                     :: "l"(p), "f"(acc.x), "f"(acc.y), "f"(acc.z), "f"(acc.w)
                     : "memory");
    }
}

__global__ void deg_kernel(const int* __restrict__ ei, float* __restrict__ deg)
{
    const int e = blockIdx.x * blockDim.x + threadIdx.x;
    if (e < NEDGES) atomicAdd(&deg[__ldg(ei + NEDGES + e)], 1.f);
}

// ---------------- fused GRU + BN + residual ----------------
__device__ __forceinline__ float gru1(float ir, float iz, float in_, float hr,
                                      float hz, float hn, float h,
                                      float ga, float be, float mu, float va)
{
    const float r = 1.f / (1.f + expf(-(ir + hr)));
    const float z = 1.f / (1.f + expf(-(iz + hz)));
    const float n = tanhf(in_ + r * hn);
    const float hnew = (1.f - z) * n + z * h;
    const float bn = (hnew - mu) * rsqrtf(va + BN_EPS) * ga + be;
    return h + bn;
}

__global__ void gru_bn_kernel(const float* __restrict__ gi, const float* __restrict__ gh,
                              float* __restrict__ h,
                              const float* __restrict__ gamma, const float* __restrict__ beta,
                              const float* __restrict__ mean,  const float* __restrict__ var)
{
    const int idx = blockIdx.x * blockDim.x + threadIdx.x;
    if (idx >= NNODES * 32) return;
    const int m = idx >> 5;
    const int c = idx & 31;
    const size_t gb = (size_t)m * 384 + c * 4;
    const float4 ir = *(const float4*)(gi + gb);
    const float4 iz = *(const float4*)(gi + gb + 128);
    const float4 in_ = *(const float4*)(gi + gb + 256);
    const float4 hr = *(const float4*)(gh + gb);
    const float4 hz = *(const float4*)(gh + gb + 128);
    const float4 hn = *(const float4*)(gh + gb + 256);
    float4 hv = *(float4*)(h + (size_t)m * 128 + c * 4);
    const float4 ga = *(const float4*)(gamma + c * 4);
    const float4 be = *(const float4*)(beta + c * 4);
    const float4 mu = *(const float4*)(mean + c * 4);
    const float4 va = *(const float4*)(var + c * 4);
    hv.x = gru1(ir.x, iz.x, in_.x, hr.x, hz.x, hn.x, hv.x, ga.x, be.x, mu.x, va.x);
    hv.y = gru1(ir.y, iz.y, in_.y, hr.y, hz.y, hn.y, hv.y, ga.y, be.y, mu.y, va.y);
    hv.z = gru1(ir.z, iz.z, in_.z, hr.z, hz.z, hn.z, hv.z, ga.z, be.z, mu.z, va.z);
    hv.w = gru1(ir.w, iz.w, in_.w, hr.w, hz.w, hn.w, hv.w, ga.w, be.w, mu.w, va.w);
    *(float4*)(h + (size_t)m * 128 + c * 4) = hv;
}

__global__ void offsets_kernel(const int* __restrict__ batch, int* __restrict__ offs)
{
    const int g = blockIdx.x * blockDim.x + threadIdx.x;
    if (g > NGRAPHS) return;
    int lo = 0, hi = NNODES;
    while (lo < hi) {
        const int mid = (lo + hi) >> 1;
        if (batch[mid] < g) lo = mid + 1; else hi = mid;
    }
    offs[g] = lo;
}

__global__ void readout_kernel(const float* __restrict__ h, const int* __restrict__ offs,
                               float* __restrict__ z)
{
    const int g = blockIdx.x;
    const int d = threadIdx.x;
    const int s0 = offs[g], e0 = offs[g + 1];
    float sum = 0.f, mx = -INFINITY;
    for (int r = s0; r < e0; ++r) {
        const float v = h[(size_t)r * 128 + d];
        sum += v;
        mx = fmaxf(mx, v);
    }
    const int cnt = e0 - s0;
    float mean = sum / fmaxf((float)cnt, 1.f);
    if (cnt == 0) { mean = 0.f; mx = 0.f; }
    z[g * 256 + d] = mean;
    z[g * 256 + 128 + d] = mx;
}

__global__ void ro_kernel(const float* __restrict__ z, const float* __restrict__ w,
                          const float* __restrict__ b, float* __restrict__ out)
{
    const int g = blockIdx.x;
    const int n = threadIdx.x;
    __shared__ float zs[256];
    zs[n] = z[g * 256 + n];
    zs[n + 128] = z[g * 256 + 128 + n];
    __syncthreads();
    float acc = b[n];
#pragma unroll 8
    for (int k = 0; k < 256; ++k)
        acc += zs[k] * w[k * 128 + n];
    out[g * 128 + n] = fmaxf(acc, 0.f);
}

// ---------------- host ----------------
static void launch_gemm(const float* A, const float* B, float* C, int M, int N,
                        int ldb, int trans, const float* bias, const float* rowScale,
                        int relu)
{
    dim3 grid((M + 127) / 128, N / 128);
    gemm_k128_kernel<<<grid, 256, GEMM_SMEM>>>(A, B, C, M, N, ldb, trans, bias,
                                               rowScale, relu);
}

extern "C" void kernel_launch(void* const* d_in, const int* in_sizes, int n_in,
                              void* d_out, int out_size)
{
    const float* x     = (const float*)d_in[0];
    const int*   ei    = (const int*)d_in[1];
    const float* ea    = (const float*)d_in[2];
    const int*   batch = (const int*)d_in[3];
    const int base = (n_in >= 21) ? 5 : 4;
    const float* lin_w  = (const float*)d_in[base + 0];
    const float* lin_b  = (const float*)d_in[base + 1];
    const float* msg_w1 = (const float*)d_in[base + 2];
    const float* msg_b1 = (const float*)d_in[base + 3];
    const float* msg_w2 = (const float*)d_in[base + 4];
    const float* msg_b2 = (const float*)d_in[base + 5];
    const float* bn_g   = (const float*)d_in[base + 6];
    const float* bn_b   = (const float*)d_in[base + 7];
    const float* bn_m   = (const float*)d_in[base + 8];
    const float* bn_v   = (const float*)d_in[base + 9];
    const float* wih    = (const float*)d_in[base + 10];
    const float* whh    = (const float*)d_in[base + 11];
    const float* bih    = (const float*)d_in[base + 12];
    const float* bhh    = (const float*)d_in[base + 13];
    const float* ro_w   = (const float*)d_in[base + 14];
    const float* ro_b   = (const float*)d_in[base + 15];
    float* out = (float*)d_out;

    float *h, *t, *s, *gi, *gh, *deg, *z;
    int* offs;
    cudaGetSymbolAddress((void**)&h,   g_h);
    cudaGetSymbolAddress((void**)&t,   g_t);
    cudaGetSymbolAddress((void**)&s,   g_s);
    cudaGetSymbolAddress((void**)&gi,  g_gi);
    cudaGetSymbolAddress((void**)&gh,  g_gh);
    cudaGetSymbolAddress((void**)&deg, g_deg);
    cudaGetSymbolAddress((void**)&offs, g_offs);
    cudaGetSymbolAddress((void**)&z,   g_z);

    cudaFuncSetAttribute(gemm_k128_kernel,
                         cudaFuncAttributeMaxDynamicSharedMemorySize, GEMM_SMEM);

    cudaMemsetAsync(deg, 0, NNODES * sizeof(float), 0);
    deg_kernel<<<(NEDGES + 255) / 256, 256>>>(ei, deg);
    offsets_kernel<<<2, 256>>>(batch, offs);

    // h = relu(x @ lin_w + lin_b)
    launch_gemm(x, lin_w, h, NNODES, HID, HID, 0, lin_b, nullptr, 1);

    for (int l = 0; l < NLAYERS; ++l) {
        const float* W1  = msg_w1 + (size_t)l * 144 * 128;
        const float* W1e = W1 + 128 * 128;
        const float* W2  = msg_w2 + (size_t)l * 128 * 128;

        launch_gemm(h, W1, t, NNODES, HID, 128, 0, msg_b1 + l * 128, nullptr, 0);
        cudaMemsetAsync(s, 0, (size_t)NNODES * HID * sizeof(float), 0);
        edge_kernel<<<1536, 256>>>(ei, ea, t, s, W1e);
        launch_gemm(s, W2, t, NNODES, HID, 128, 0, msg_b2 + l * 128, deg, 0);
        launch_gemm(t, wih + (size_t)l * 384 * 128, gi, NNODES, 384, 128, 1,
                    bih + l * 384, nullptr, 0);
        launch_gemm(h, whh + (size_t)l * 384 * 128, gh, NNODES, 384, 128, 1,
                    bhh + l * 384, nullptr, 0);
        gru_bn_kernel<<<(NNODES * 32 + 255) / 256, 256>>>(
            gi, gh, h, bn_g + l * 128, bn_b + l * 128, bn_m + l * 128, bn_v + l * 128);
    }

    readout_kernel<<<NGRAPHS, 128>>>(h, offs, z);
    ro_kernel<<<NGRAPHS, 128>>>(z, ro_w, ro_b, out);
}

// round 6
// speedup vs baseline: 2.0142x; 2.0142x over previous
#include <cuda_runtime.h>
#include <cuda_bf16.h>
#include <math.h>
#include <stdint.h>

#define NNODES 50000
#define NEDGES 800000
#define HID    128
#define NLAYERS 3
#define NGRAPHS 256
#define BN_EPS 1e-5f

// ---------------- scratch ----------------
__device__ float g_h[NNODES * HID];
__device__ float g_t[NNODES * HID];
__device__ float g_s[NNODES * HID];
__device__ float g_gi[NNODES * 3 * HID];
__device__ float g_gh[NNODES * 3 * HID];
__device__ float g_deg[NNODES];
__device__ int   g_offs[NGRAPHS + 1];
__device__ float g_z[NGRAPHS * 2 * HID];
// bf16 hi/lo weights, [n][k=128] row-major. rows: lin=128, per layer 1024.
#define WROWS 3200
__device__ __nv_bfloat16 g_wh[WROWS * 128];
__device__ __nv_bfloat16 g_wl[WROWS * 128];

__device__ __forceinline__ uint32_t smem_u32(const void* p) {
    uint32_t a;
    asm("{ .reg .u64 t; cvta.to.shared.u64 t, %1; cvt.u32.u64 %0, t; }"
        : "=r"(a) : "l"(p));
    return a;
}
__device__ __forceinline__ uint32_t pkbf(__nv_bfloat16 a, __nv_bfloat16 b) {
    __nv_bfloat162 t; t.x = a; t.y = b;
    return *(uint32_t*)&t;
}

// swizzled byte addr of 16B chunk (row, c) in a [128 rows][16 chunks] tile
#define SW_ADDR(row, c) (((row) << 8) + ((((c) ^ ((row) & 7))) << 4))

#define LDMX4(r0, r1, r2, r3, ad)                                            \
    asm volatile("ldmatrix.sync.aligned.m8n8.x4.shared.b16 {%0,%1,%2,%3}, [%4];" \
                 : "=r"(r0), "=r"(r1), "=r"(r2), "=r"(r3) : "r"(ad))

#define MMA16816(d, a, b)                                                    \
    asm volatile("mma.sync.aligned.m16n8k16.row.col.f32.bf16.bf16.f32 "      \
                 "{%0,%1,%2,%3}, {%4,%5,%6,%7}, {%8,%9}, {%0,%1,%2,%3};"     \
                 : "+f"((d)[0]), "+f"((d)[1]), "+f"((d)[2]), "+f"((d)[3])    \
                 : "r"((a)[0]), "r"((a)[1]), "r"((a)[2]), "r"((a)[3]),       \
                   "r"((b)[0]), "r"((b)[1]))

// ---------------- weight pre-conversion ----------------
// in [K=128][N] f32 -> out [N][128] bf16 hi/lo (transpose)
__global__ void wconv_tr(const float* __restrict__ in, int N,
                         __nv_bfloat16* __restrict__ oh, __nv_bfloat16* __restrict__ ol)
{
    const int idx = blockIdx.x * 256 + threadIdx.x;
    if (idx >= N * 128) return;
    const int n = idx >> 7, k = idx & 127;
    const float v = in[(size_t)k * N + n];
    const __nv_bfloat16 h = __float2bfloat16_rn(v);
    oh[idx] = h;
    ol[idx] = __float2bfloat16_rn(v - __bfloat162float(h));
}
// in [N][128] f32 -> out [N][128] bf16 hi/lo (direct)
__global__ void wconv_nt(const float* __restrict__ in, int total,
                         __nv_bfloat16* __restrict__ oh, __nv_bfloat16* __restrict__ ol)
{
    const int idx = blockIdx.x * 256 + threadIdx.x;
    if (idx >= total) return;
    const float v = in[idx];
    const __nv_bfloat16 h = __float2bfloat16_rn(v);
    oh[idx] = h;
    ol[idx] = __float2bfloat16_rn(v - __bfloat162float(h));
}

// ---------------- bf16-split tensor-core GEMM ----------------
// C[M,N] = A[M,128] @ W^T  (W = [N][128] bf16 hi/lo)
// epilogue: + bias[n] * (rowScale ? rowScale[m] : 1), optional relu
// block: 128(M) x 128(N), 256 threads (8 warps, 4x2), full K in smem.
// smem: Ahi@0 Alo@32768 Bhi@65536 Blo@98304  (131072 total)
#define MG_SMEM 131072

__global__ void __launch_bounds__(256, 1)
mma_gemm(const float* __restrict__ A, const __nv_bfloat16* __restrict__ Bh,
         const __nv_bfloat16* __restrict__ Bl, float* __restrict__ C,
         int M, int N, const float* __restrict__ bias,
         const float* __restrict__ rowScale, int doRelu)
{
    extern __shared__ char sm[];
    const int tid = threadIdx.x;
    const int m0 = blockIdx.x * 128;
    const int n0 = blockIdx.y * 128;

    // ---- fill A (f32 -> bf16 hi/lo, swizzled chunks) ----
#pragma unroll
    for (int p = 0; p < 8; ++p) {
        const int idx = tid + p * 256;     // 2048 chunks
        const int m = idx >> 4, c = idx & 15;
        const int gm = m0 + m;
        float4 v0 = make_float4(0.f, 0.f, 0.f, 0.f), v1 = v0;
        if (gm < M) {
            v0 = *(const float4*)(A + (size_t)gm * 128 + c * 8);
            v1 = *(const float4*)(A + (size_t)gm * 128 + c * 8 + 4);
        }
        const float f[8] = {v0.x, v0.y, v0.z, v0.w, v1.x, v1.y, v1.z, v1.w};
        __nv_bfloat16 h[8], l[8];
#pragma unroll
        for (int j = 0; j < 8; ++j) {
            h[j] = __float2bfloat16_rn(f[j]);
            l[j] = __float2bfloat16_rn(f[j] - __bfloat162float(h[j]));
        }
        uint4 hv, lv;
        hv.x = pkbf(h[0], h[1]); hv.y = pkbf(h[2], h[3]);
        hv.z = pkbf(h[4], h[5]); hv.w = pkbf(h[6], h[7]);
        lv.x = pkbf(l[0], l[1]); lv.y = pkbf(l[2], l[3]);
        lv.z = pkbf(l[4], l[5]); lv.w = pkbf(l[6], l[7]);
        const int a = SW_ADDR(m, c);
        *(uint4*)(sm + a)         = hv;
        *(uint4*)(sm + 32768 + a) = lv;
    }
    // ---- fill B (already bf16, plain chunk copy, swizzled) ----
#pragma unroll
    for (int p = 0; p < 16; ++p) {
        const int idx = tid + p * 256;     // 4096 chunk copies (hi then lo)
        const int half = idx >> 11;
        const int r = (idx >> 4) & 127, c = idx & 15;
        const __nv_bfloat16* src = half ? Bl : Bh;
        const uint4 v = *(const uint4*)(src + (size_t)(n0 + r) * 128 + c * 8);
        *(uint4*)(sm + (half ? 98304 : 65536) + SW_ADDR(r, c)) = v;
    }
    __syncthreads();

    const int wid = tid >> 5, L = tid & 31;
    const int wm = (wid & 3) * 32;    // warp M offset
    const int wn = (wid >> 2) * 64;   // warp N offset
    const uint32_t smb = smem_u32(sm);

    float acc[2][8][4];
#pragma unroll
    for (int i = 0; i < 2; ++i)
#pragma unroll
        for (int j = 0; j < 8; ++j)
#pragma unroll
            for (int q = 0; q < 4; ++q) acc[i][j][q] = 0.f;

    const int arow = wm + (L & 15);
    const int acs  = L >> 4;
    const int brow = wn + (L & 7) + ((L & 16) ? 8 : 0);
    const int bcs  = (L >> 3) & 1;

#pragma unroll
    for (int ks = 0; ks < 8; ++ks) {
        const int c0 = ks * 2;
        uint32_t Ah[2][4], Al[2][4];
#pragma unroll
        for (int mf = 0; mf < 2; ++mf) {
            const uint32_t off = SW_ADDR(arow + mf * 16, c0 + acs);
            LDMX4(Ah[mf][0], Ah[mf][1], Ah[mf][2], Ah[mf][3], smb + off);
            LDMX4(Al[mf][0], Al[mf][1], Al[mf][2], Al[mf][3], smb + 32768 + off);
        }
        uint32_t Bhf[8][2], Blf[8][2];
#pragma unroll
        for (int nf = 0; nf < 4; ++nf) {
            const uint32_t off = SW_ADDR(brow + nf * 16, c0 + bcs);
            LDMX4(Bhf[nf * 2][0], Bhf[nf * 2][1], Bhf[nf * 2 + 1][0],
                  Bhf[nf * 2 + 1][1], smb + 65536 + off);
            LDMX4(Blf[nf * 2][0], Blf[nf * 2][1], Blf[nf * 2 + 1][0],
                  Blf[nf * 2 + 1][1], smb + 98304 + off);
        }
#pragma unroll
        for (int mf = 0; mf < 2; ++mf)
#pragma unroll
            for (int j = 0; j < 8; ++j) {
                MMA16816(acc[mf][j], Ah[mf], Bhf[j]);
                MMA16816(acc[mf][j], Ah[mf], Blf[j]);
                MMA16816(acc[mf][j], Al[mf], Bhf[j]);
            }
    }

    // ---- epilogue ----
#pragma unroll
    for (int mf = 0; mf < 2; ++mf) {
        const int rbase = m0 + wm + mf * 16 + (L >> 2);
#pragma unroll
        for (int half = 0; half < 2; ++half) {
            const int r = rbase + half * 8;
            if (r >= M) continue;
            const float rs = rowScale ? __ldg(rowScale + r) : 1.f;
#pragma unroll
            for (int j = 0; j < 8; ++j) {
                const int col = n0 + wn + j * 8 + 2 * (L & 3);
                float o0 = acc[mf][j][half * 2]     + __ldg(bias + col)     * rs;
                float o1 = acc[mf][j][half * 2 + 1] + __ldg(bias + col + 1) * rs;
                if (doRelu) { o0 = fmaxf(o0, 0.f); o1 = fmaxf(o1, 0.f); }
                *(float2*)(C + (size_t)r * N + col) = make_float2(o0, o1);
            }
        }
    }
}

// ---------------- per-edge: u = relu(t[src] + ea@W1e); s[dst] += u ----------
__global__ void __launch_bounds__(256)
edge_kernel(const int* __restrict__ ei, const float* __restrict__ ea,
            const float* __restrict__ t, float* __restrict__ s,
            const float* __restrict__ w1e)
{
    const int lane = threadIdx.x & 31;
    float4 w[16];
#pragma unroll
    for (int j = 0; j < 16; ++j)
        w[j] = *(const float4*)(w1e + j * 128 + lane * 4);

    const int warp = blockIdx.x * (blockDim.x >> 5) + (threadIdx.x >> 5);
    const int nw = gridDim.x * (blockDim.x >> 5);
    for (int e = warp; e < NEDGES; e += nw) {
        const int src = __ldg(ei + e);
        const int dst = __ldg(ei + NEDGES + e);
        float4 acc = *(const float4*)(t + (size_t)src * 128 + lane * 4);
        const float4* ev = (const float4*)(ea + (size_t)e * 16);
#pragma unroll
        for (int q = 0; q < 4; ++q) {
            const float4 e4 = __ldg(ev + q);
            const float4 w0 = w[q * 4 + 0], w1 = w[q * 4 + 1];
            const float4 w2 = w[q * 4 + 2], w3 = w[q * 4 + 3];
            acc.x += e4.x * w0.x + e4.y * w1.x + e4.z * w2.x + e4.w * w3.x;
            acc.y += e4.x * w0.y + e4.y * w1.y + e4.z * w2.y + e4.w * w3.y;
            acc.z += e4.x * w0.z + e4.y * w1.z + e4.z * w2.z + e4.w * w3.z;
            acc.w += e4.x * w0.w + e4.y * w1.w + e4.z * w2.w + e4.w * w3.w;
        }
        acc.x = fmaxf(acc.x, 0.f); acc.y = fmaxf(acc.y, 0.f);
        acc.z = fmaxf(acc.z, 0.f); acc.w = fmaxf(acc.w, 0.f);
        float* p = s + (size_t)dst * 128 + lane * 4;
        asm volatile("red.global.add.v4.f32 [%0], {%1,%2,%3,%4};"
                     :: "l"(p), "f"(acc.x), "f"(acc.y), "f"(acc.z), "f"(acc.w)
                     : "memory");
    }
}

__global__ void deg_kernel(const int* __restrict__ ei, float* __restrict__ deg)
{
    const int e = blockIdx.x * blockDim.x + threadIdx.x;
    if (e < NEDGES) atomicAdd(&deg[__ldg(ei + NEDGES + e)], 1.f);
}

// ---------------- fused GRU + BN + residual ----------------
__device__ __forceinline__ float gru1(float ir, float iz, float in_, float hr,
                                      float hz, float hn, float h,
                                      float ga, float be, float mu, float va)
{
    const float r = 1.f / (1.f + expf(-(ir + hr)));
    const float z = 1.f / (1.f + expf(-(iz + hz)));
    const float n = tanhf(in_ + r * hn);
    const float hnew = (1.f - z) * n + z * h;
    const float bn = (hnew - mu) * rsqrtf(va + BN_EPS) * ga + be;
    return h + bn;
}

__global__ void gru_bn_kernel(const float* __restrict__ gi, const float* __restrict__ gh,
                              float* __restrict__ h,
                              const float* __restrict__ gamma, const float* __restrict__ beta,
                              const float* __restrict__ mean,  const float* __restrict__ var)
{
    const int idx = blockIdx.x * blockDim.x + threadIdx.x;
    if (idx >= NNODES * 32) return;
    const int m = idx >> 5;
    const int c = idx & 31;
    const size_t gb = (size_t)m * 384 + c * 4;
    const float4 ir = *(const float4*)(gi + gb);
    const float4 iz = *(const float4*)(gi + gb + 128);
    const float4 in_ = *(const float4*)(gi + gb + 256);
    const float4 hr = *(const float4*)(gh + gb);
    const float4 hz = *(const float4*)(gh + gb + 128);
    const float4 hn = *(const float4*)(gh + gb + 256);
    float4 hv = *(float4*)(h + (size_t)m * 128 + c * 4);
    const float4 ga = *(const float4*)(gamma + c * 4);
    const float4 be = *(const float4*)(beta + c * 4);
    const float4 mu = *(const float4*)(mean + c * 4);
    const float4 va = *(const float4*)(var + c * 4);
    hv.x = gru1(ir.x, iz.x, in_.x, hr.x, hz.x, hn.x, hv.x, ga.x, be.x, mu.x, va.x);
    hv.y = gru1(ir.y, iz.y, in_.y, hr.y, hz.y, hn.y, hv.y, ga.y, be.y, mu.y, va.y);
    hv.z = gru1(ir.z, iz.z, in_.z, hr.z, hz.z, hn.z, hv.z, ga.z, be.z, mu.z, va.z);
    hv.w = gru1(ir.w, iz.w, in_.w, hr.w, hz.w, hn.w, hv.w, ga.w, be.w, mu.w, va.w);
    *(float4*)(h + (size_t)m * 128 + c * 4) = hv;
}

__global__ void offsets_kernel(const int* __restrict__ batch, int* __restrict__ offs)
{
    const int g = blockIdx.x * blockDim.x + threadIdx.x;
    if (g > NGRAPHS) return;
    int lo = 0, hi = NNODES;
    while (lo < hi) {
        const int mid = (lo + hi) >> 1;
        if (batch[mid] < g) lo = mid + 1; else hi = mid;
    }
    offs[g] = lo;
}

__global__ void readout_kernel(const float* __restrict__ h, const int* __restrict__ offs,
                               float* __restrict__ z)
{
    const int g = blockIdx.x;
    const int d = threadIdx.x;
    const int s0 = offs[g], e0 = offs[g + 1];
    float sum = 0.f, mx = -INFINITY;
    for (int r = s0; r < e0; ++r) {
        const float v = h[(size_t)r * 128 + d];
        sum += v;
        mx = fmaxf(mx, v);
    }
    const int cnt = e0 - s0;
    float mean = sum / fmaxf((float)cnt, 1.f);
    if (cnt == 0) { mean = 0.f; mx = 0.f; }
    z[g * 256 + d] = mean;
    z[g * 256 + 128 + d] = mx;
}

__global__ void ro_kernel(const float* __restrict__ z, const float* __restrict__ w,
                          const float* __restrict__ b, float* __restrict__ out)
{
    const int g = blockIdx.x;
    const int n = threadIdx.x;
    __shared__ float zs[256];
    zs[n] = z[g * 256 + n];
    zs[n + 128] = z[g * 256 + 128 + n];
    __syncthreads();
    float acc = b[n];
#pragma unroll 8
    for (int k = 0; k < 256; ++k)
        acc += zs[k] * w[k * 128 + n];
    out[g * 128 + n] = fmaxf(acc, 0.f);
}

// ---------------- host ----------------
static void launch_mma(const float* A, const __nv_bfloat16* wh, const __nv_bfloat16* wl,
                       int wrow, float* C, int M, int N, const float* bias,
                       const float* rowScale, int relu)
{
    dim3 grid((M + 127) / 128, N / 128);
    mma_gemm<<<grid, 256, MG_SMEM>>>(A, wh + (size_t)wrow * 128,
                                     wl + (size_t)wrow * 128, C, M, N, bias,
                                     rowScale, relu);
}

extern "C" void kernel_launch(void* const* d_in, const int* in_sizes, int n_in,
                              void* d_out, int out_size)
{
    const float* x     = (const float*)d_in[0];
    const int*   ei    = (const int*)d_in[1];
    const float* ea    = (const float*)d_in[2];
    const int*   batch = (const int*)d_in[3];
    const int base = (n_in >= 21) ? 5 : 4;
    const float* lin_w  = (const float*)d_in[base + 0];
    const float* lin_b  = (const float*)d_in[base + 1];
    const float* msg_w1 = (const float*)d_in[base + 2];
    const float* msg_b1 = (const float*)d_in[base + 3];
    const float* msg_w2 = (const float*)d_in[base + 4];
    const float* msg_b2 = (const float*)d_in[base + 5];
    const float* bn_g   = (const float*)d_in[base + 6];
    const float* bn_b   = (const float*)d_in[base + 7];
    const float* bn_m   = (const float*)d_in[base + 8];
    const float* bn_v   = (const float*)d_in[base + 9];
    const float* wih    = (const float*)d_in[base + 10];
    const float* whh    = (const float*)d_in[base + 11];
    const float* bih    = (const float*)d_in[base + 12];
    const float* bhh    = (const float*)d_in[base + 13];
    const float* ro_w   = (const float*)d_in[base + 14];
    const float* ro_b   = (const float*)d_in[base + 15];
    float* out = (float*)d_out;

    float *h, *t, *s, *gi, *gh, *deg, *z;
    int* offs;
    __nv_bfloat16 *wh_, *wl_;
    cudaGetSymbolAddress((void**)&h,   g_h);
    cudaGetSymbolAddress((void**)&t,   g_t);
    cudaGetSymbolAddress((void**)&s,   g_s);
    cudaGetSymbolAddress((void**)&gi,  g_gi);
    cudaGetSymbolAddress((void**)&gh,  g_gh);
    cudaGetSymbolAddress((void**)&deg, g_deg);
    cudaGetSymbolAddress((void**)&offs, g_offs);
    cudaGetSymbolAddress((void**)&z,   g_z);
    cudaGetSymbolAddress((void**)&wh_, g_wh);
    cudaGetSymbolAddress((void**)&wl_, g_wl);

    cudaFuncSetAttribute(mma_gemm,
                         cudaFuncAttributeMaxDynamicSharedMemorySize, MG_SMEM);

    // ---- weight pre-conversion (row offsets into g_wh/g_wl) ----
    // lin: 0 ; layer l: w1h = 128 + l*1024, w2 = +128, wih = +256, whh = +640
    wconv_tr<<<64, 256>>>(lin_w, 128, wh_, wl_);
    for (int l = 0; l < NLAYERS; ++l) {
        const int b0 = 128 + l * 1024;
        wconv_tr<<<64, 256>>>(msg_w1 + (size_t)l * 144 * 128, 128,
                              wh_ + (size_t)b0 * 128, wl_ + (size_t)b0 * 128);
        wconv_tr<<<64, 256>>>(msg_w2 + (size_t)l * 128 * 128, 128,
                              wh_ + (size_t)(b0 + 128) * 128, wl_ + (size_t)(b0 + 128) * 128);
        wconv_nt<<<192, 256>>>(wih + (size_t)l * 384 * 128, 384 * 128,
                               wh_ + (size_t)(b0 + 256) * 128, wl_ + (size_t)(b0 + 256) * 128);
        wconv_nt<<<192, 256>>>(whh + (size_t)l * 384 * 128, 384 * 128,
                               wh_ + (size_t)(b0 + 640) * 128, wl_ + (size_t)(b0 + 640) * 128);
    }

    cudaMemsetAsync(deg, 0, NNODES * sizeof(float), 0);
    deg_kernel<<<(NEDGES + 255) / 256, 256>>>(ei, deg);
    offsets_kernel<<<2, 256>>>(batch, offs);

    // h = relu(x @ lin_w + lin_b)
    launch_mma(x, wh_, wl_, 0, h, NNODES, 128, lin_b, nullptr, 1);

    for (int l = 0; l < NLAYERS; ++l) {
        const int b0 = 128 + l * 1024;
        const float* W1e = msg_w1 + (size_t)l * 144 * 128 + 128 * 128;

        launch_mma(h, wh_, wl_, b0, t, NNODES, 128, msg_b1 + l * 128, nullptr, 0);
        cudaMemsetAsync(s, 0, (size_t)NNODES * HID * sizeof(float), 0);
        edge_kernel<<<1536, 256>>>(ei, ea, t, s, W1e);
        launch_mma(s, wh_, wl_, b0 + 128, t, NNODES, 128, msg_b2 + l * 128, deg, 0);
        launch_mma(t, wh_, wl_, b0 + 256, gi, NNODES, 384, bih + l * 384, nullptr, 0);
        launch_mma(h, wh_, wl_, b0 + 640, gh, NNODES, 384, bhh + l * 384, nullptr, 0);
        gru_bn_kernel<<<(NNODES * 32 + 255) / 256, 256>>>(
            gi, gh, h, bn_g + l * 128, bn_b + l * 128, bn_m + l * 128, bn_v + l * 128);
    }

    readout_kernel<<<NGRAPHS, 128>>>(h, offs, z);
    ro_kernel<<<NGRAPHS, 128>>>(z, ro_w, ro_b, out);
}

// round 7
// speedup vs baseline: 2.0841x; 1.0347x over previous
#include <cuda_runtime.h>
#include <cuda_bf16.h>
#include <math.h>
#include <stdint.h>

#define NNODES 50000
#define NEDGES 800000
#define HID    128
#define NLAYERS 3
#define NGRAPHS 256
#define BN_EPS 1e-5f

// ---------------- scratch ----------------
__device__ float g_h[NNODES * HID];
__device__ float g_t[NNODES * HID];
__device__ float g_s[NNODES * HID];
__device__ float g_gi[NNODES * 3 * HID];
__device__ float g_gh[NNODES * 3 * HID];
__device__ float g_deg[NNODES];
__device__ int   g_offs[NGRAPHS + 1];
__device__ float g_z[NGRAPHS * 2 * HID];
__device__ float g_bc[NLAYERS * 384];          // folded bias b2@wih^T
// bf16 hi/lo weights, [n][k=128]. rows: lin 0..127, w1h 128..511,
// wc 512..1663, whh 1664..2815
#define WROWS 2816
__device__ __nv_bfloat16 g_wh[WROWS * 128];
__device__ __nv_bfloat16 g_wl[WROWS * 128];

__device__ __forceinline__ uint32_t smem_u32(const void* p) {
    uint32_t a;
    asm("{ .reg .u64 t; cvta.to.shared.u64 t, %1; cvt.u32.u64 %0, t; }"
        : "=r"(a) : "l"(p));
    return a;
}
__device__ __forceinline__ uint32_t pkbf(__nv_bfloat16 a, __nv_bfloat16 b) {
    __nv_bfloat162 t; t.x = a; t.y = b;
    return *(uint32_t*)&t;
}

// swizzled byte addr of 16B chunk (row, c) in [rows][16 chunk] tile
#define SW_ADDR(row, c) (((row) << 8) + ((((c) ^ ((row) & 7))) << 4))

#define LDMX4(r0, r1, r2, r3, ad)                                            \
    asm volatile("ldmatrix.sync.aligned.m8n8.x4.shared.b16 {%0,%1,%2,%3}, [%4];" \
                 : "=r"(r0), "=r"(r1), "=r"(r2), "=r"(r3) : "r"(ad))

#define MMA16816(d, a, b)                                                    \
    asm volatile("mma.sync.aligned.m16n8k16.row.col.f32.bf16.bf16.f32 "      \
                 "{%0,%1,%2,%3}, {%4,%5,%6,%7}, {%8,%9}, {%0,%1,%2,%3};"     \
                 : "+f"((d)[0]), "+f"((d)[1]), "+f"((d)[2]), "+f"((d)[3])    \
                 : "r"((a)[0]), "r"((a)[1]), "r"((a)[2]), "r"((a)[3]),       \
                   "r"((b)[0]), "r"((b)[1]))

// ---------------- weight pre-conversion ----------------
__global__ void wconv_tr(const float* __restrict__ in, int N,
                         __nv_bfloat16* __restrict__ oh, __nv_bfloat16* __restrict__ ol)
{
    const int idx = blockIdx.x * 256 + threadIdx.x;
    if (idx >= N * 128) return;
    const int n = idx >> 7, k = idx & 127;
    const float v = in[(size_t)k * N + n];
    const __nv_bfloat16 h = __float2bfloat16_rn(v);
    oh[idx] = h;
    ol[idx] = __float2bfloat16_rn(v - __bfloat162float(h));
}
__global__ void wconv_nt(const float* __restrict__ in, int total,
                         __nv_bfloat16* __restrict__ oh, __nv_bfloat16* __restrict__ ol)
{
    const int idx = blockIdx.x * 256 + threadIdx.x;
    if (idx >= total) return;
    const float v = in[idx];
    const __nv_bfloat16 h = __float2bfloat16_rn(v);
    oh[idx] = h;
    ol[idx] = __float2bfloat16_rn(v - __bfloat162float(h));
}
// Wc^T[n][j] = sum_o W2[j][o]*wih[n][o]; bc[n] = sum_o b2[o]*wih[n][o]
__global__ void wc_kernel(const float* __restrict__ w2, const float* __restrict__ wih,
                          const float* __restrict__ b2,
                          __nv_bfloat16* __restrict__ oh, __nv_bfloat16* __restrict__ ol,
                          float* __restrict__ bc)
{
    const int n = blockIdx.x;      // 384
    const int j = threadIdx.x;     // 128
    __shared__ float wr[128];
    __shared__ float red[128];
    wr[j] = wih[(size_t)n * 128 + j];
    __syncthreads();
    float acc = 0.f;
    const float* w2r = w2 + (size_t)j * 128;
#pragma unroll 8
    for (int o = 0; o < 128; ++o) acc += w2r[o] * wr[o];
    const __nv_bfloat16 h = __float2bfloat16_rn(acc);
    oh[(size_t)n * 128 + j] = h;
    ol[(size_t)n * 128 + j] = __float2bfloat16_rn(acc - __bfloat162float(h));
    // bc reduction
    red[j] = b2[j] * wr[j];
    __syncthreads();
    for (int st = 64; st > 0; st >>= 1) {
        if (j < st) red[j] += red[j + st];
        __syncthreads();
    }
    if (j == 0) bc[n] = red[0];
}

// ---------------- bf16-split tensor-core GEMM ----------------
// C[M,N] = A[M,128] @ W^T  (W = [N][128] bf16 hi/lo)
// epilogue: + bias1[n] + bias2[n]*rowScale[m], optional relu
// block: 64(M) x 128(N), 256 threads (8 warps 2x4), full K in smem, occ 2.
// smem: Ahi@0(16K) Alo@16384 Bhi@32768(32K) Blo@65536 -> 98304
#define MG_SMEM 98304

__global__ void __launch_bounds__(256, 2)
mma_gemm(const float* __restrict__ A, const __nv_bfloat16* __restrict__ Bh,
         const __nv_bfloat16* __restrict__ Bl, float* __restrict__ C,
         int M, int N, const float* __restrict__ bias1,
         const float* __restrict__ bias2, const float* __restrict__ rowScale,
         int doRelu)
{
    extern __shared__ char sm[];
    const int tid = threadIdx.x;
    const int m0 = blockIdx.x * 64;
    const int n0 = blockIdx.y * 128;

    // ---- fill A (f32 -> bf16 hi/lo, swizzled) : 64 rows x 16 chunks ----
#pragma unroll
    for (int p = 0; p < 4; ++p) {
        const int idx = tid + p * 256;     // 1024 chunks
        const int m = idx >> 4, c = idx & 15;
        const int gm = m0 + m;
        float4 v0 = make_float4(0.f, 0.f, 0.f, 0.f), v1 = v0;
        if (gm < M) {
            v0 = *(const float4*)(A + (size_t)gm * 128 + c * 8);
            v1 = *(const float4*)(A + (size_t)gm * 128 + c * 8 + 4);
        }
        const float f[8] = {v0.x, v0.y, v0.z, v0.w, v1.x, v1.y, v1.z, v1.w};
        __nv_bfloat16 h[8], l[8];
#pragma unroll
        for (int j = 0; j < 8; ++j) {
            h[j] = __float2bfloat16_rn(f[j]);
            l[j] = __float2bfloat16_rn(f[j] - __bfloat162float(h[j]));
        }
        uint4 hv, lv;
        hv.x = pkbf(h[0], h[1]); hv.y = pkbf(h[2], h[3]);
        hv.z = pkbf(h[4], h[5]); hv.w = pkbf(h[6], h[7]);
        lv.x = pkbf(l[0], l[1]); lv.y = pkbf(l[2], l[3]);
        lv.z = pkbf(l[4], l[5]); lv.w = pkbf(l[6], l[7]);
        const int a = SW_ADDR(m, c);
        *(uint4*)(sm + a)         = hv;
        *(uint4*)(sm + 16384 + a) = lv;
    }
    // ---- fill B (bf16 copy, swizzled) : 128 rows x 16 chunks x {hi,lo} ----
#pragma unroll
    for (int p = 0; p < 16; ++p) {
        const int idx = tid + p * 256;     // 4096
        const int half = idx >> 11;
        const int r = (idx >> 4) & 127, c = idx & 15;
        const __nv_bfloat16* src = half ? Bl : Bh;
        const uint4 v = *(const uint4*)(src + (size_t)(n0 + r) * 128 + c * 8);
        *(uint4*)(sm + (half ? 65536 : 32768) + SW_ADDR(r, c)) = v;
    }
    __syncthreads();

    const int wid = tid >> 5, L = tid & 31;
    const int wm = (wid & 1) * 32;     // warp M offset (2 warps over 64)
    const int wn = (wid >> 1) * 32;    // warp N offset (4 warps over 128)
    const uint32_t smb = smem_u32(sm);

    float acc[2][4][4];
#pragma unroll
    for (int i = 0; i < 2; ++i)
#pragma unroll
        for (int j = 0; j < 4; ++j)
#pragma unroll
            for (int q = 0; q < 4; ++q) acc[i][j][q] = 0.f;

    const int arow = wm + (L & 15);
    const int acs  = L >> 4;
    const int brow = wn + (L & 7) + ((L & 16) ? 8 : 0);
    const int bcs  = (L >> 3) & 1;

#pragma unroll
    for (int ks = 0; ks < 8; ++ks) {
        const int c0 = ks * 2;
        uint32_t Ah[2][4], Al[2][4];
#pragma unroll
        for (int mf = 0; mf < 2; ++mf) {
            const uint32_t off = SW_ADDR(arow + mf * 16, c0 + acs);
            LDMX4(Ah[mf][0], Ah[mf][1], Ah[mf][2], Ah[mf][3], smb + off);
            LDMX4(Al[mf][0], Al[mf][1], Al[mf][2], Al[mf][3], smb + 16384 + off);
        }
        uint32_t Bhf[4][2], Blf[4][2];
#pragma unroll
        for (int nf = 0; nf < 2; ++nf) {
            const uint32_t off = SW_ADDR(brow + nf * 16, c0 + bcs);
            LDMX4(Bhf[nf * 2][0], Bhf[nf * 2][1], Bhf[nf * 2 + 1][0],
                  Bhf[nf * 2 + 1][1], smb + 32768 + off);
            LDMX4(Blf[nf * 2][0], Blf[nf * 2][1], Blf[nf * 2 + 1][0],
                  Blf[nf * 2 + 1][1], smb + 65536 + off);
        }
#pragma unroll
        for (int mf = 0; mf < 2; ++mf)
#pragma unroll
            for (int j = 0; j < 4; ++j) {
                MMA16816(acc[mf][j], Ah[mf], Bhf[j]);
                MMA16816(acc[mf][j], Ah[mf], Blf[j]);
                MMA16816(acc[mf][j], Al[mf], Bhf[j]);
            }
    }

    // ---- epilogue: acc + bias1[n] + bias2[n]*rowScale[m] ----
#pragma unroll
    for (int mf = 0; mf < 2; ++mf) {
        const int rbase = m0 + wm + mf * 16 + (L >> 2);
#pragma unroll
        for (int half = 0; half < 2; ++half) {
            const int r = rbase + half * 8;
            if (r >= M) continue;
            const float rs = rowScale ? __ldg(rowScale + r) : 0.f;
#pragma unroll
            for (int j = 0; j < 4; ++j) {
                const int col = n0 + wn + j * 8 + 2 * (L & 3);
                float b0 = bias1 ? __ldg(bias1 + col)     : 0.f;
                float b1 = bias1 ? __ldg(bias1 + col + 1) : 0.f;
                if (bias2) {
                    b0 += __ldg(bias2 + col)     * rs;
                    b1 += __ldg(bias2 + col + 1) * rs;
                }
                float o0 = acc[mf][j][half * 2]     + b0;
                float o1 = acc[mf][j][half * 2 + 1] + b1;
                if (doRelu) { o0 = fmaxf(o0, 0.f); o1 = fmaxf(o1, 0.f); }
                *(float2*)(C + (size_t)r * N + col) = make_float2(o0, o1);
            }
        }
    }
}

// ---------------- per-edge: u = relu(t[src] + ea@W1e); s[dst] += u ----------
__global__ void __launch_bounds__(256)
edge_kernel(const int* __restrict__ ei, const float* __restrict__ ea,
            const float* __restrict__ t, float* __restrict__ s,
            const float* __restrict__ w1e)
{
    const int lane = threadIdx.x & 31;
    float4 w[16];
#pragma unroll
    for (int j = 0; j < 16; ++j)
        w[j] = *(const float4*)(w1e + j * 128 + lane * 4);

    const int warp = blockIdx.x * (blockDim.x >> 5) + (threadIdx.x >> 5);
    const int nw = gridDim.x * (blockDim.x >> 5);
    for (int e = warp; e < NEDGES; e += nw) {
        const int src = __ldg(ei + e);
        const int dst = __ldg(ei + NEDGES + e);
        float4 acc = *(const float4*)(t + (size_t)src * 128 + lane * 4);
        const float4* ev = (const float4*)(ea + (size_t)e * 16);
#pragma unroll
        for (int q = 0; q < 4; ++q) {
            const float4 e4 = __ldg(ev + q);
            const float4 w0 = w[q * 4 + 0], w1 = w[q * 4 + 1];
            const float4 w2 = w[q * 4 + 2], w3 = w[q * 4 + 3];
            acc.x += e4.x * w0.x + e4.y * w1.x + e4.z * w2.x + e4.w * w3.x;
            acc.y += e4.x * w0.y + e4.y * w1.y + e4.z * w2.y + e4.w * w3.y;
            acc.z += e4.x * w0.z + e4.y * w1.z + e4.z * w2.z + e4.w * w3.z;
            acc.w += e4.x * w0.w + e4.y * w1.w + e4.z * w2.w + e4.w * w3.w;
        }
        acc.x = fmaxf(acc.x, 0.f); acc.y = fmaxf(acc.y, 0.f);
        acc.z = fmaxf(acc.z, 0.f); acc.w = fmaxf(acc.w, 0.f);
        float* p = s + (size_t)dst * 128 + lane * 4;
        asm volatile("red.global.add.v4.f32 [%0], {%1,%2,%3,%4};"
                     :: "l"(p), "f"(acc.x), "f"(acc.y), "f"(acc.z), "f"(acc.w)
                     : "memory");
    }
}

__global__ void deg_kernel(const int* __restrict__ ei, float* __restrict__ deg)
{
    const int e = blockIdx.x * blockDim.x + threadIdx.x;
    if (e < NEDGES) atomicAdd(&deg[__ldg(ei + NEDGES + e)], 1.f);
}

// ---------------- fused GRU + BN + residual ----------------
__device__ __forceinline__ float gru1(float ir, float iz, float in_, float hr,
                                      float hz, float hn, float h,
                                      float ga, float be, float mu, float va)
{
    const float r = 1.f / (1.f + expf(-(ir + hr)));
    const float z = 1.f / (1.f + expf(-(iz + hz)));
    const float n = tanhf(in_ + r * hn);
    const float hnew = (1.f - z) * n + z * h;
    const float bn = (hnew - mu) * rsqrtf(va + BN_EPS) * ga + be;
    return h + bn;
}

__global__ void gru_bn_kernel(const float* __restrict__ gi, const float* __restrict__ gh,
                              float* __restrict__ h,
                              const float* __restrict__ gamma, const float* __restrict__ beta,
                              const float* __restrict__ mean,  const float* __restrict__ var)
{
    const int idx = blockIdx.x * blockDim.x + threadIdx.x;
    if (idx >= NNODES * 32) return;
    const int m = idx >> 5;
    const int c = idx & 31;
    const size_t gb = (size_t)m * 384 + c * 4;
    const float4 ir = *(const float4*)(gi + gb);
    const float4 iz = *(const float4*)(gi + gb + 128);
    const float4 in_ = *(const float4*)(gi + gb + 256);
    const float4 hr = *(const float4*)(gh + gb);
    const float4 hz = *(const float4*)(gh + gb + 128);
    const float4 hn = *(const float4*)(gh + gb + 256);
    float4 hv = *(float4*)(h + (size_t)m * 128 + c * 4);
    const float4 ga = *(const float4*)(gamma + c * 4);
    const float4 be = *(const float4*)(beta + c * 4);
    const float4 mu = *(const float4*)(mean + c * 4);
    const float4 va = *(const float4*)(var + c * 4);
    hv.x = gru1(ir.x, iz.x, in_.x, hr.x, hz.x, hn.x, hv.x, ga.x, be.x, mu.x, va.x);
    hv.y = gru1(ir.y, iz.y, in_.y, hr.y, hz.y, hn.y, hv.y, ga.y, be.y, mu.y, va.y);
    hv.z = gru1(ir.z, iz.z, in_.z, hr.z, hz.z, hn.z, hv.z, ga.z, be.z, mu.z, va.z);
    hv.w = gru1(ir.w, iz.w, in_.w, hr.w, hz.w, hn.w, hv.w, ga.w, be.w, mu.w, va.w);
    *(float4*)(h + (size_t)m * 128 + c * 4) = hv;
}

__global__ void offsets_kernel(const int* __restrict__ batch, int* __restrict__ offs)
{
    const int g = blockIdx.x * blockDim.x + threadIdx.x;
    if (g > NGRAPHS) return;
    int lo = 0, hi = NNODES;
    while (lo < hi) {
        const int mid = (lo + hi) >> 1;
        if (batch[mid] < g) lo = mid + 1; else hi = mid;
    }
    offs[g] = lo;
}

__global__ void readout_kernel(const float* __restrict__ h, const int* __restrict__ offs,
                               float* __restrict__ z)
{
    const int g = blockIdx.x;
    const int d = threadIdx.x;
    const int s0 = offs[g], e0 = offs[g + 1];
    float sum = 0.f, mx = -INFINITY;
    for (int r = s0; r < e0; ++r) {
        const float v = h[(size_t)r * 128 + d];
        sum += v;
        mx = fmaxf(mx, v);
    }
    const int cnt = e0 - s0;
    float mean = sum / fmaxf((float)cnt, 1.f);
    if (cnt == 0) { mean = 0.f; mx = 0.f; }
    z[g * 256 + d] = mean;
    z[g * 256 + 128 + d] = mx;
}

__global__ void ro_kernel(const float* __restrict__ z, const float* __restrict__ w,
                          const float* __restrict__ b, float* __restrict__ out)
{
    const int g = blockIdx.x;
    const int n = threadIdx.x;
    __shared__ float zs[256];
    zs[n] = z[g * 256 + n];
    zs[n + 128] = z[g * 256 + 128 + n];
    __syncthreads();
    float acc = b[n];
#pragma unroll 8
    for (int k = 0; k < 256; ++k)
        acc += zs[k] * w[k * 128 + n];
    out[g * 128 + n] = fmaxf(acc, 0.f);
}

// ---------------- host ----------------
static void launch_mma(const float* A, const __nv_bfloat16* wh, const __nv_bfloat16* wl,
                       int wrow, float* C, int M, int N, const float* bias1,
                       const float* bias2, const float* rowScale, int relu)
{
    dim3 grid((M + 63) / 64, N / 128);
    mma_gemm<<<grid, 256, MG_SMEM>>>(A, wh + (size_t)wrow * 128,
                                     wl + (size_t)wrow * 128, C, M, N, bias1,
                                     bias2, rowScale, relu);
}

extern "C" void kernel_launch(void* const* d_in, const int* in_sizes, int n_in,
                              void* d_out, int out_size)
{
    const float* x     = (const float*)d_in[0];
    const int*   ei    = (const int*)d_in[1];
    const float* ea    = (const float*)d_in[2];
    const int*   batch = (const int*)d_in[3];
    const int base = (n_in >= 21) ? 5 : 4;
    const float* lin_w  = (const float*)d_in[base + 0];
    const float* lin_b  = (const float*)d_in[base + 1];
    const float* msg_w1 = (const float*)d_in[base + 2];
    const float* msg_b1 = (const float*)d_in[base + 3];
    const float* msg_w2 = (const float*)d_in[base + 4];
    const float* msg_b2 = (const float*)d_in[base + 5];
    const float* bn_g   = (const float*)d_in[base + 6];
    const float* bn_b   = (const float*)d_in[base + 7];
    const float* bn_m   = (const float*)d_in[base + 8];
    const float* bn_v   = (const float*)d_in[base + 9];
    const float* wih    = (const float*)d_in[base + 10];
    const float* whh    = (const float*)d_in[base + 11];
    const float* bih    = (const float*)d_in[base + 12];
    const float* bhh    = (const float*)d_in[base + 13];
    const float* ro_w   = (const float*)d_in[base + 14];
    const float* ro_b   = (const float*)d_in[base + 15];
    float* out = (float*)d_out;

    float *h, *t, *s, *gi, *gh, *deg, *z, *bc;
    int* offs;
    __nv_bfloat16 *wh_, *wl_;
    cudaGetSymbolAddress((void**)&h,   g_h);
    cudaGetSymbolAddress((void**)&t,   g_t);
    cudaGetSymbolAddress((void**)&s,   g_s);
    cudaGetSymbolAddress((void**)&gi,  g_gi);
    cudaGetSymbolAddress((void**)&gh,  g_gh);
    cudaGetSymbolAddress((void**)&deg, g_deg);
    cudaGetSymbolAddress((void**)&offs, g_offs);
    cudaGetSymbolAddress((void**)&z,   g_z);
    cudaGetSymbolAddress((void**)&bc,  g_bc);
    cudaGetSymbolAddress((void**)&wh_, g_wh);
    cudaGetSymbolAddress((void**)&wl_, g_wl);

    cudaFuncSetAttribute(mma_gemm,
                         cudaFuncAttributeMaxDynamicSharedMemorySize, MG_SMEM);

    // ---- weight prep ----
    wconv_tr<<<64, 256>>>(lin_w, 128, wh_, wl_);                    // rows 0..127
    for (int l = 0; l < NLAYERS; ++l) {
        wconv_tr<<<64, 256>>>(msg_w1 + (size_t)l * 144 * 128, 128,  // w1h rows
                              wh_ + (size_t)(128 + l * 128) * 128,
                              wl_ + (size_t)(128 + l * 128) * 128);
        wc_kernel<<<384, 128>>>(msg_w2 + (size_t)l * 128 * 128,     // wc rows
                                wih + (size_t)l * 384 * 128, msg_b2 + l * 128,
                                wh_ + (size_t)(512 + l * 384) * 128,
                                wl_ + (size_t)(512 + l * 384) * 128,
                                bc + l * 384);
    }
    wconv_nt<<<576, 256>>>(whh, NLAYERS * 384 * 128,                // whh rows
                           wh_ + (size_t)1664 * 128, wl_ + (size_t)1664 * 128);

    cudaMemsetAsync(deg, 0, NNODES * sizeof(float), 0);
    deg_kernel<<<(NEDGES + 255) / 256, 256>>>(ei, deg);
    offsets_kernel<<<2, 256>>>(batch, offs);

    // h = relu(x @ lin_w + lin_b)
    launch_mma(x, wh_, wl_, 0, h, NNODES, 128, lin_b, nullptr, nullptr, 1);

    for (int l = 0; l < NLAYERS; ++l) {
        const float* W1e = msg_w1 + (size_t)l * 144 * 128 + 128 * 128;

        // t = h @ W1h + b1
        launch_mma(h, wh_, wl_, 128 + l * 128, t, NNODES, 128,
                   msg_b1 + l * 128, nullptr, nullptr, 0);
        cudaMemsetAsync(s, 0, (size_t)NNODES * HID * sizeof(float), 0);
        edge_kernel<<<1536, 256>>>(ei, ea, t, s, W1e);
        // gi = s @ Wc + bih + deg*bc   (agg GEMM folded away)
        launch_mma(s, wh_, wl_, 512 + l * 384, gi, NNODES, 384,
                   bih + l * 384, bc + l * 384, deg, 0);
        // gh = h @ whh^T + bhh
        launch_mma(h, wh_, wl_, 1664 + l * 384, gh, NNODES, 384,
                   bhh + l * 384, nullptr, nullptr, 0);
        gru_bn_kernel<<<(NNODES * 32 + 255) / 256, 256>>>(
            gi, gh, h, bn_g + l * 128, bn_b + l * 128, bn_m + l * 128, bn_v + l * 128);
    }

    readout_kernel<<<NGRAPHS, 128>>>(h, offs, z);
    ro_kernel<<<NGRAPHS, 128>>>(z, ro_w, ro_b, out);
}